// round 1
// baseline (speedup 1.0000x reference)
#include <cuda_runtime.h>

// Problem constants
#define BATCH 1024
#define NIN   1152
#define DIN   8
#define NOUT  10
#define DOUT  16

// Tiling
#define NCHUNK 18
#define CI     (NIN / NCHUNK)   // 64 input capsules per chunk
#define TB     32               // batches per CTA
#define BTILES (BATCH / TB)     // 32

// Deterministic reduction scratch + routing state (static device memory; no allocs)
__device__ float g_partial[NCHUNK][BATCH][NOUT][DOUT];  // ~11.8 MB
__device__ float g_pden[NCHUNK][BATCH][NOUT];           // ~0.74 MB
__device__ float g_vsum[BATCH][NOUT][DOUT];             // ~0.66 MB

// One routing pass: for each (b, i, n) recompute u_hat[n,:] = W[i,n,:,:] @ x[b,i,:],
// logit = <u_hat, Vsum>, w = exp(logit); accumulate w*u_hat and w.
// FIRST=true: b==0 => uniform weights (w=1), skip Vsum/dot/exp entirely.
template <bool FIRST>
__global__ void __launch_bounds__(TB * NOUT)
route_pass(const float* __restrict__ x, const float* __restrict__ W)
{
    const int tid   = threadIdx.x;
    const int n     = tid >> 5;          // warp id 0..9 -> output capsule
    const int lane  = tid & 31;          // batch within tile
    const int b     = blockIdx.y * TB + lane;
    const int chunk = blockIdx.x;
    const int i0    = chunk * CI;

    float vs[DOUT];
    if (!FIRST) {
#pragma unroll
        for (int d = 0; d < DOUT; d++) vs[d] = g_vsum[b][n][d];
    }

    float acc[DOUT];
#pragma unroll
    for (int d = 0; d < DOUT; d++) acc[d] = 0.0f;
    float accd = 0.0f;

    const float4* __restrict__ xg =
        reinterpret_cast<const float4*>(x + (size_t)b * NIN * DIN);

#pragma unroll 2
    for (int ii = 0; ii < CI; ii++) {
        const int i = i0 + ii;
        // x[b,i,0:8]
        const float4 xa = xg[i * 2 + 0];
        const float4 xb = xg[i * 2 + 1];
        // W[i,n,:,:] : 16 rows x 8 (e contiguous). All 32 lanes in this warp
        // share (i,n) -> broadcast loads, served from L2/L1.
        const float4* __restrict__ wr =
            reinterpret_cast<const float4*>(W + ((size_t)i * NOUT + n) * (DOUT * DIN));

        float u[DOUT];
#pragma unroll
        for (int d = 0; d < DOUT; d++) {
            const float4 w0 = wr[d * 2 + 0];
            const float4 w1 = wr[d * 2 + 1];
            u[d] = xa.x * w0.x + xa.y * w0.y + xa.z * w0.z + xa.w * w0.w
                 + xb.x * w1.x + xb.y * w1.y + xb.z * w1.z + xb.w * w1.w;
        }

        float wgt;
        if (FIRST) {
            wgt = 1.0f;
        } else {
            float bl = 0.0f;
#pragma unroll
            for (int d = 0; d < DOUT; d++) bl += u[d] * vs[d];
            wgt = __expf(bl);   // softmax max-shift unnecessary: |bl| is O(10)
        }

#pragma unroll
        for (int d = 0; d < DOUT; d++) acc[d] += wgt * u[d];
        accd += wgt;
    }

#pragma unroll
    for (int d = 0; d < DOUT; d++) g_partial[chunk][b][n][d] = acc[d];
    g_pden[chunk][b][n] = accd;
}

// Reduce partials, apply squash, update Vsum (or write final output).
// grid = BATCH, block = 160 threads: tid -> (n = tid/16, d = tid%16).
template <bool FIRST, bool LAST>
__global__ void __launch_bounds__(NOUT * DOUT)
squash_update(float* __restrict__ out)
{
    const int b = blockIdx.x;
    const int tid = threadIdx.x;
    const int n = tid >> 4;
    const int d = tid & 15;

    float num = 0.0f;
#pragma unroll
    for (int c = 0; c < NCHUNK; c++) num += g_partial[c][b][n][d];
    float den = 0.0f;
#pragma unroll
    for (int c = 0; c < NCHUNK; c++) den += g_pden[c][b][n];

    const float s = num / den;

    // squared-norm over the 16 lanes sharing n (lanes [0..15] / [16..31] of a warp)
    float s2 = s * s;
#pragma unroll
    for (int off = 8; off; off >>= 1) s2 += __shfl_xor_sync(0xffffffffu, s2, off);

    const float scale = s2 / (1.0f + s2) * rsqrtf(s2 + 1e-7f);
    const float v = scale * s;

    if (LAST) {
        out[((size_t)b * NOUT + n) * DOUT + d] = v;
    } else if (FIRST) {
        g_vsum[b][n][d] = v;
    } else {
        g_vsum[b][n][d] += v;
    }
}

extern "C" void kernel_launch(void* const* d_in, const int* in_sizes, int n_in,
                              void* d_out, int out_size)
{
    // Inputs: x [1024,1152,8] (9437184 elems), W [1,1152,10,16,8] (1474560 elems).
    const float* x;
    const float* W;
    if (in_sizes[0] == BATCH * NIN * DIN) {
        x = (const float*)d_in[0];
        W = (const float*)d_in[1];
    } else {
        x = (const float*)d_in[1];
        W = (const float*)d_in[0];
    }
    float* out = (float*)d_out;

    dim3 grid(NCHUNK, BTILES);
    const int threads = TB * NOUT;

    // iter 0 (uniform weights), iter 1, iter 2 (final)
    route_pass<true ><<<grid, threads>>>(x, W);
    squash_update<true , false><<<BATCH, NOUT * DOUT>>>(out);

    route_pass<false><<<grid, threads>>>(x, W);
    squash_update<false, false><<<BATCH, NOUT * DOUT>>>(out);

    route_pass<false><<<grid, threads>>>(x, W);
    squash_update<false, true ><<<BATCH, NOUT * DOUT>>>(out);
}

// round 2
// speedup vs baseline: 1.2705x; 1.2705x over previous
#include <cuda_runtime.h>

#define BATCH 1024
#define NIN   1152
#define DIN   8
#define NOUT  10
#define DOUT  16
#define QTOT  (NIN * DIN)        // 9216
#define NCHUNK 18
#define CI     (NIN / NCHUNK)    // 64
#define TB     32
#define BTILES (BATCH / TB)      // 32

typedef unsigned long long u64;

// Static device scratch (no allocations allowed)
__device__ float g_xt[QTOT][BATCH];                     // x transposed: [i*8+e][b]  (36 MB)
__device__ float g_Wt[NIN * NOUT * DIN * DOUT];         // W transposed: [i][n][e][d] (5.9 MB)
__device__ float g_partial[NCHUNK][BATCH][NOUT][DOUT];  // 11.8 MB
__device__ float g_pden[NCHUNK][BATCH][NOUT];
__device__ float g_vsum[BATCH][NOUT][DOUT];

// ---- packed f32x2 helpers (PTX-only on sm_103a; 2x fp32 FMA throughput) ----
__device__ __forceinline__ u64 fma2(u64 a, u64 b, u64 c) {
    u64 d; asm("fma.rn.f32x2 %0,%1,%2,%3;" : "=l"(d) : "l"(a), "l"(b), "l"(c)); return d;
}
__device__ __forceinline__ u64 mul2(u64 a, u64 b) {
    u64 d; asm("mul.rn.f32x2 %0,%1,%2;" : "=l"(d) : "l"(a), "l"(b)); return d;
}
__device__ __forceinline__ u64 add2(u64 a, u64 b) {
    u64 d; asm("add.rn.f32x2 %0,%1,%2;" : "=l"(d) : "l"(a), "l"(b)); return d;
}
__device__ __forceinline__ u64 dup2(float x) {
    u64 d; asm("mov.b64 %0,{%1,%1};" : "=l"(d) : "f"(x)); return d;
}
__device__ __forceinline__ float hadd2(u64 a) {
    float lo, hi; asm("mov.b64 {%0,%1},%2;" : "=f"(lo), "=f"(hi) : "l"(a)); return lo + hi;
}

// ---- x transpose: x[b][q] -> g_xt[q][b], tiled through smem ----
__global__ void transpose_x(const float* __restrict__ x)
{
    __shared__ float t[32][33];
    const int q0 = blockIdx.x * 32;
    const int b0 = blockIdx.y * 32;
    const int lane = threadIdx.x & 31;
    const int w = threadIdx.x >> 5;          // 8 warps
#pragma unroll
    for (int r = w; r < 32; r += 8)
        t[r][lane] = x[(size_t)(b0 + r) * QTOT + q0 + lane];
    __syncthreads();
#pragma unroll
    for (int r = w; r < 32; r += 8)
        g_xt[q0 + r][b0 + lane] = t[lane][r];
}

// ---- W transpose: W[in][d][e] -> g_Wt[in][e][d]  (in = i*NOUT+n) ----
__global__ void transpose_W(const float* __restrict__ W)
{
    const int g = blockIdx.x * 256 + threadIdx.x;   // over 1,474,560 (out-coalesced)
    const int d = g & 15;
    const int e = (g >> 4) & 7;
    const int in = g >> 7;
    g_Wt[g] = W[(size_t)in * 128 + d * 8 + e];
}

// ---- One routing pass (streaming softmax; u_hat recomputed, never stored) ----
// warp = output capsule n, lane = batch within tile. All math packed f32x2 over d-pairs.
template <bool FIRST>
__global__ void __launch_bounds__(TB * NOUT, 2)
route_pass()
{
    const int n    = threadIdx.x >> 5;
    const int lane = threadIdx.x & 31;
    const int b    = blockIdx.y * TB + lane;
    const int i0   = blockIdx.x * CI;

    u64 vs2[8];
    if (!FIRST) {
        const ulonglong2* vp = reinterpret_cast<const ulonglong2*>(&g_vsum[b][n][0]);
#pragma unroll
        for (int k = 0; k < 4; k++) { ulonglong2 t = vp[k]; vs2[2 * k] = t.x; vs2[2 * k + 1] = t.y; }
    }

    u64 acc2[8];
#pragma unroll
    for (int k = 0; k < 8; k++) acc2[k] = 0ull;
    float accd = 0.0f;

#pragma unroll 2
    for (int ii = 0; ii < CI; ii++) {
        const int i = i0 + ii;

        // coalesced x loads: lanes (batches) contiguous in g_xt
        float xv[8];
#pragma unroll
        for (int e = 0; e < 8; e++) xv[e] = g_xt[i * 8 + e][b];

        // W row pointer for (i, n): [e][d] with d contiguous
        const ulonglong2* __restrict__ wp =
            reinterpret_cast<const ulonglong2*>(&g_Wt[(size_t)(i * NOUT + n) * (DIN * DOUT)]);

        u64 u2[8];  // u_hat packed over d-pairs
#pragma unroll
        for (int e = 0; e < 8; e++) {
            const u64 xd = dup2(xv[e]);
            const ulonglong2 w0 = wp[e * 4 + 0];
            const ulonglong2 w1 = wp[e * 4 + 1];
            const ulonglong2 w2 = wp[e * 4 + 2];
            const ulonglong2 w3 = wp[e * 4 + 3];
            if (e == 0) {
                u2[0] = mul2(xd, w0.x); u2[1] = mul2(xd, w0.y);
                u2[2] = mul2(xd, w1.x); u2[3] = mul2(xd, w1.y);
                u2[4] = mul2(xd, w2.x); u2[5] = mul2(xd, w2.y);
                u2[6] = mul2(xd, w3.x); u2[7] = mul2(xd, w3.y);
            } else {
                u2[0] = fma2(xd, w0.x, u2[0]); u2[1] = fma2(xd, w0.y, u2[1]);
                u2[2] = fma2(xd, w1.x, u2[2]); u2[3] = fma2(xd, w1.y, u2[3]);
                u2[4] = fma2(xd, w2.x, u2[4]); u2[5] = fma2(xd, w2.y, u2[5]);
                u2[6] = fma2(xd, w3.x, u2[6]); u2[7] = fma2(xd, w3.y, u2[7]);
            }
        }

        if (FIRST) {
#pragma unroll
            for (int k = 0; k < 8; k++) acc2[k] = add2(acc2[k], u2[k]);
        } else {
            u64 l2 = mul2(u2[0], vs2[0]);
#pragma unroll
            for (int k = 1; k < 8; k++) l2 = fma2(u2[k], vs2[k], l2);
            const float wgt = __expf(hadd2(l2));   // logits are O(10): no max-shift needed
            const u64 wd = dup2(wgt);
#pragma unroll
            for (int k = 0; k < 8; k++) acc2[k] = fma2(wd, u2[k], acc2[k]);
            accd += wgt;
        }
    }

    ulonglong2* pp = reinterpret_cast<ulonglong2*>(&g_partial[blockIdx.x][b][n][0]);
    pp[0] = make_ulonglong2(acc2[0], acc2[1]);
    pp[1] = make_ulonglong2(acc2[2], acc2[3]);
    pp[2] = make_ulonglong2(acc2[4], acc2[5]);
    pp[3] = make_ulonglong2(acc2[6], acc2[7]);
    g_pden[blockIdx.x][b][n] = FIRST ? (float)CI : accd;
}

// ---- Reduce partials, squash, update Vsum / write output ----
template <bool FIRST, bool LAST>
__global__ void __launch_bounds__(NOUT * DOUT)
squash_update(float* __restrict__ out)
{
    const int b = blockIdx.x;
    const int tid = threadIdx.x;
    const int n = tid >> 4;
    const int d = tid & 15;

    float num = 0.0f;
#pragma unroll
    for (int c = 0; c < NCHUNK; c++) num += g_partial[c][b][n][d];
    float den = 0.0f;
#pragma unroll
    for (int c = 0; c < NCHUNK; c++) den += g_pden[c][b][n];

    const float s = num / den;

    float s2 = s * s;
#pragma unroll
    for (int off = 8; off; off >>= 1) s2 += __shfl_xor_sync(0xffffffffu, s2, off);

    const float scale = s2 / (1.0f + s2) * rsqrtf(s2 + 1e-7f);
    const float v = scale * s;

    if (LAST)       out[((size_t)b * NOUT + n) * DOUT + d] = v;
    else if (FIRST) g_vsum[b][n][d] = v;
    else            g_vsum[b][n][d] += v;
}

extern "C" void kernel_launch(void* const* d_in, const int* in_sizes, int n_in,
                              void* d_out, int out_size)
{
    const float* x;
    const float* W;
    if (in_sizes[0] == BATCH * NIN * DIN) { x = (const float*)d_in[0]; W = (const float*)d_in[1]; }
    else                                  { x = (const float*)d_in[1]; W = (const float*)d_in[0]; }
    float* out = (float*)d_out;

    transpose_x<<<dim3(QTOT / 32, BATCH / 32), 256>>>(x);
    transpose_W<<<(NIN * NOUT * DIN * DOUT) / 256, 256>>>(W);

    dim3 grid(NCHUNK, BTILES);
    const int threads = TB * NOUT;

    route_pass<true ><<<grid, threads>>>();
    squash_update<true , false><<<BATCH, NOUT * DOUT>>>(out);

    route_pass<false><<<grid, threads>>>();
    squash_update<false, false><<<BATCH, NOUT * DOUT>>>(out);

    route_pass<false><<<grid, threads>>>();
    squash_update<false, true ><<<BATCH, NOUT * DOUT>>>(out);
}

// round 3
// speedup vs baseline: 2.1004x; 1.6532x over previous
#include <cuda_runtime.h>

#define BATCH 1024
#define NIN   1152
#define DIN   8
#define NOUT  10
#define DOUT  16
#define QTOT  (NIN * DIN)        // 9216
#define NCHUNK 18
#define CI     (NIN / NCHUNK)    // 64
#define TB     32
#define BTILES (BATCH / TB)      // 32
#define SI     4                 // i's per smem sub-tile
#define NSUB   (CI / SI)         // 16

typedef unsigned long long u64;

// Static device scratch (no allocations allowed)
__device__ float g_xt[QTOT][BATCH];                     // x^T: [i*8+e][b]  (36 MB)
__device__ float g_Wt[NIN * NOUT * DIN * DOUT];         // W^T: [i][n][e][d] (5.9 MB)
__device__ float g_partial[NCHUNK][BATCH][NOUT][DOUT];
__device__ float g_pden[NCHUNK][BATCH][NOUT];
__device__ float g_vsum[BATCH][NOUT][DOUT];

// ---- packed f32x2 helpers (PTX-only on sm_103a; 2x fp32 FMA throughput) ----
__device__ __forceinline__ u64 fma2(u64 a, u64 b, u64 c) {
    u64 d; asm("fma.rn.f32x2 %0,%1,%2,%3;" : "=l"(d) : "l"(a), "l"(b), "l"(c)); return d;
}
__device__ __forceinline__ u64 mul2(u64 a, u64 b) {
    u64 d; asm("mul.rn.f32x2 %0,%1,%2;" : "=l"(d) : "l"(a), "l"(b)); return d;
}
__device__ __forceinline__ u64 add2(u64 a, u64 b) {
    u64 d; asm("add.rn.f32x2 %0,%1,%2;" : "=l"(d) : "l"(a), "l"(b)); return d;
}
__device__ __forceinline__ u64 dup2(float x) {
    u64 d; asm("mov.b64 %0,{%1,%1};" : "=l"(d) : "f"(x)); return d;
}
__device__ __forceinline__ float hadd2(u64 a) {
    float lo, hi; asm("mov.b64 {%0,%1},%2;" : "=f"(lo), "=f"(hi) : "l"(a)); return lo + hi;
}

// ---- cp.async helpers ----
__device__ __forceinline__ void cpa16(void* smem_dst, const void* gmem_src) {
    unsigned s = (unsigned)__cvta_generic_to_shared(smem_dst);
    asm volatile("cp.async.cg.shared.global [%0], [%1], 16;" :: "r"(s), "l"(gmem_src));
}
__device__ __forceinline__ void cpa_commit() { asm volatile("cp.async.commit_group;"); }
template <int N> __device__ __forceinline__ void cpa_wait() {
    asm volatile("cp.async.wait_group %0;" :: "n"(N));
}

// ---- x transpose: x[b][q] -> g_xt[q][b] ----
__global__ void transpose_x(const float* __restrict__ x)
{
    __shared__ float t[32][33];
    const int q0 = blockIdx.x * 32;
    const int b0 = blockIdx.y * 32;
    const int lane = threadIdx.x & 31;
    const int w = threadIdx.x >> 5;
#pragma unroll
    for (int r = w; r < 32; r += 8)
        t[r][lane] = x[(size_t)(b0 + r) * QTOT + q0 + lane];
    __syncthreads();
#pragma unroll
    for (int r = w; r < 32; r += 8)
        g_xt[q0 + r][b0 + lane] = t[lane][r];
}

// ---- W transpose: W[in][d][e] -> g_Wt[in][e][d]  (in = i*NOUT+n) ----
__global__ void transpose_W(const float* __restrict__ W)
{
    const int g = blockIdx.x * 256 + threadIdx.x;
    const int d = g & 15;
    const int e = (g >> 4) & 7;
    const int in = g >> 7;
    g_Wt[g] = W[(size_t)in * 128 + d * 8 + e];
}

// ---- One routing pass: W through double-buffered smem, x via L1 LDG ----
// warp = output capsule n, lane = batch. All d-math packed f32x2.
template <bool FIRST>
__global__ void __launch_bounds__(TB * NOUT, 2)
route_pass()
{
    // smem W sub-tile: [buf][i_local][n][16 ulonglong2(=128 floats)]
    __shared__ ulonglong2 ws[2][SI * NOUT * 32];

    const int tid  = threadIdx.x;
    const int n    = tid >> 5;
    const int lane = tid & 31;
    const int b    = blockIdx.y * TB + lane;
    const int i0   = blockIdx.x * CI;

    // sub-tile fill: SI*10*128 floats = 5120 f = 1280 x 16B; 320 threads -> 4 each
    const float* __restrict__ wbase = g_Wt + (size_t)i0 * NOUT * 128;

    // prefetch sub 0
#pragma unroll
    for (int k = 0; k < 4; k++)
        cpa16(((char*)ws[0]) + (tid + k * 320) * 16,
              (const char*)wbase + (tid + k * 320) * 16);
    cpa_commit();

    u64 vs2[8];
    if (!FIRST) {
        const ulonglong2* vp = reinterpret_cast<const ulonglong2*>(&g_vsum[b][n][0]);
#pragma unroll
        for (int k = 0; k < 4; k++) { ulonglong2 t = vp[k]; vs2[2*k] = t.x; vs2[2*k+1] = t.y; }
    }

    u64 acc2[8];
#pragma unroll
    for (int k = 0; k < 8; k++) acc2[k] = 0ull;
    float accd = 0.0f;

    for (int s = 0; s < NSUB; s++) {
        // prefetch next sub-tile
        if (s + 1 < NSUB) {
            const float* src = wbase + (size_t)(s + 1) * SI * NOUT * 128;
#pragma unroll
            for (int k = 0; k < 4; k++)
                cpa16(((char*)ws[(s + 1) & 1]) + (tid + k * 320) * 16,
                      (const char*)src + (size_t)(tid + k * 320) * 16);
            cpa_commit();
            cpa_wait<1>();
        } else {
            cpa_wait<0>();
        }
        __syncthreads();

        const ulonglong2* __restrict__ wsb = ws[s & 1];

#pragma unroll 2
        for (int ii = 0; ii < SI; ii++) {
            const int i = i0 + s * SI + ii;

            float xv[8];
#pragma unroll
            for (int e = 0; e < 8; e++) xv[e] = g_xt[i * 8 + e][b];

            const ulonglong2* __restrict__ wp = wsb + (ii * NOUT + n) * 32;

            u64 u2[8];
#pragma unroll
            for (int e = 0; e < 8; e++) {
                const u64 xd = dup2(xv[e]);
                const ulonglong2 w0 = wp[e * 4 + 0];
                const ulonglong2 w1 = wp[e * 4 + 1];
                const ulonglong2 w2 = wp[e * 4 + 2];
                const ulonglong2 w3 = wp[e * 4 + 3];
                if (e == 0) {
                    u2[0] = mul2(xd, w0.x); u2[1] = mul2(xd, w0.y);
                    u2[2] = mul2(xd, w1.x); u2[3] = mul2(xd, w1.y);
                    u2[4] = mul2(xd, w2.x); u2[5] = mul2(xd, w2.y);
                    u2[6] = mul2(xd, w3.x); u2[7] = mul2(xd, w3.y);
                } else {
                    u2[0] = fma2(xd, w0.x, u2[0]); u2[1] = fma2(xd, w0.y, u2[1]);
                    u2[2] = fma2(xd, w1.x, u2[2]); u2[3] = fma2(xd, w1.y, u2[3]);
                    u2[4] = fma2(xd, w2.x, u2[4]); u2[5] = fma2(xd, w2.y, u2[5]);
                    u2[6] = fma2(xd, w3.x, u2[6]); u2[7] = fma2(xd, w3.y, u2[7]);
                }
            }

            if (FIRST) {
#pragma unroll
                for (int k = 0; k < 8; k++) acc2[k] = add2(acc2[k], u2[k]);
            } else {
                u64 l2 = mul2(u2[0], vs2[0]);
#pragma unroll
                for (int k = 1; k < 8; k++) l2 = fma2(u2[k], vs2[k], l2);
                const float wgt = __expf(hadd2(l2));  // logits O(10): no max-shift needed
                const u64 wd = dup2(wgt);
#pragma unroll
                for (int k = 0; k < 8; k++) acc2[k] = fma2(wd, u2[k], acc2[k]);
                accd += wgt;
            }
        }
        __syncthreads();   // all warps done with buf[s&1] before its refill next iter
    }

    ulonglong2* pp = reinterpret_cast<ulonglong2*>(&g_partial[blockIdx.x][b][n][0]);
    pp[0] = make_ulonglong2(acc2[0], acc2[1]);
    pp[1] = make_ulonglong2(acc2[2], acc2[3]);
    pp[2] = make_ulonglong2(acc2[4], acc2[5]);
    pp[3] = make_ulonglong2(acc2[6], acc2[7]);
    g_pden[blockIdx.x][b][n] = FIRST ? (float)CI : accd;
}

// ---- Reduce partials, squash, update Vsum / write output ----
template <bool FIRST, bool LAST>
__global__ void __launch_bounds__(NOUT * DOUT)
squash_update(float* __restrict__ out)
{
    const int b = blockIdx.x;
    const int tid = threadIdx.x;
    const int n = tid >> 4;
    const int d = tid & 15;

    float num = 0.0f;
#pragma unroll
    for (int c = 0; c < NCHUNK; c++) num += g_partial[c][b][n][d];
    float den = 0.0f;
#pragma unroll
    for (int c = 0; c < NCHUNK; c++) den += g_pden[c][b][n];

    const float s = num / den;

    float s2 = s * s;
#pragma unroll
    for (int off = 8; off; off >>= 1) s2 += __shfl_xor_sync(0xffffffffu, s2, off);

    const float scale = s2 / (1.0f + s2) * rsqrtf(s2 + 1e-7f);
    const float v = scale * s;

    if (LAST)       out[((size_t)b * NOUT + n) * DOUT + d] = v;
    else if (FIRST) g_vsum[b][n][d] = v;
    else            g_vsum[b][n][d] += v;
}

extern "C" void kernel_launch(void* const* d_in, const int* in_sizes, int n_in,
                              void* d_out, int out_size)
{
    const float* x;
    const float* W;
    if (in_sizes[0] == BATCH * NIN * DIN) { x = (const float*)d_in[0]; W = (const float*)d_in[1]; }
    else                                  { x = (const float*)d_in[1]; W = (const float*)d_in[0]; }
    float* out = (float*)d_out;

    transpose_x<<<dim3(QTOT / 32, BATCH / 32), 256>>>(x);
    transpose_W<<<(NIN * NOUT * DIN * DOUT) / 256, 256>>>(W);

    dim3 grid(NCHUNK, BTILES);
    const int threads = TB * NOUT;

    route_pass<true ><<<grid, threads>>>();
    squash_update<true , false><<<BATCH, NOUT * DOUT>>>(out);

    route_pass<false><<<grid, threads>>>();
    squash_update<false, false><<<BATCH, NOUT * DOUT>>>(out);

    route_pass<false><<<grid, threads>>>();
    squash_update<false, true ><<<BATCH, NOUT * DOUT>>>(out);
}